// round 15
// baseline (speedup 1.0000x reference)
#include <cuda_runtime.h>
#include <math.h>

#define N        2048
#define THREADS  256
#define EPN      8
#define FULLM    0xFFFFFFFFu

typedef unsigned int   u32;
typedef unsigned short u16;

__device__ __forceinline__ float logaddexpf_(float a, float b) {
    float mx = fmaxf(a, b);
    float mn = fminf(a, b);
    return mx + __logf(1.0f + __expf(mn - mx));
}

// One stable 9-bit radix pass on u32 keys, in-place.
// Item order contract: items[e] is sorted-position warp*256 + e*32 + lane.
// If SWZ: scatter writes key for position p at swizzled address
//   sigma(p) = (p&~255)|((p&31)<<3)|((p>>5)&7), so next gather is 2x LDS.128.
// If LAST: scatter emits s/perm at TRUE positions via theta[idx].
template <bool LAST, bool SWZ, int SHIFT, bool MASK>
__device__ __forceinline__ void radix_pass9(
    const u32 items[EPN],
    u16* __restrict__ whist, int* __restrict__ dbase, int* __restrict__ scrI,
    u32* __restrict__ keyA, float* __restrict__ s_arr, u16* __restrict__ perm,
    const float* __restrict__ theta,
    int tid, int warp, int lane, u32 lt)
{
    // zero OWN warp's histogram row (1024B = 64 uint4); __syncwarp suffices.
    {
        uint4 z = make_uint4(0, 0, 0, 0);
        uint4* wz = (uint4*)(whist + (warp << 9));
        wz[lane]      = z;
        wz[lane + 32] = z;
        __syncwarp();
    }

    // ranking: per-warp running counts; processing order == position order
    u16* wrow = whist + warp * 512;
    u32 lr0 = 0, lr1 = 0;
    #pragma unroll
    for (int e = 0; e < EPN; ++e) {
        int d = MASK ? ((int)(items[e] >> SHIFT) & 511) : (int)(items[e] >> SHIFT);
        u32 m = __match_any_sync(FULLM, d);
        int lr = __popc(m & lt);
        u32 prior = wrow[d];
        u32 rk = prior + (u32)lr;           // within-warp stable rank for digit d
        if (e < 4) lr0 |= rk << (e * 8);
        else       lr1 |= rk << ((e - 4) * 8);
        if ((m & lt) == 0)                  // leader bumps running count
            wrow[d] = (u16)(prior + __popc(m));
        __syncwarp();
    }
    __syncthreads();   // all gathers complete too (in-place safety)

    // distributed scan: warp w owns digits [64w, 64w+64), 2 per lane.
    {
        int d0 = (warp << 6) + lane;
        int d1 = d0 + 32;
        u32 run0 = 0, run1 = 0;
        #pragma unroll
        for (int w8 = 0; w8 < 8; ++w8) {
            u16* rowp = whist + (w8 << 9);
            u32 v0 = rowp[d0]; rowp[d0] = (u16)run0; run0 += v0;
            u32 v1 = rowp[d1]; rowp[d1] = (u16)run1; run1 += v1;
        }
        u32 a = run0, ai = a;
        #pragma unroll
        for (int o = 1; o < 32; o <<= 1) { u32 t = __shfl_up_sync(FULLM, ai, o); if (lane >= o) ai += t; }
        u32 tA = __shfl_sync(FULLM, ai, 31);
        u32 b = run1, bi = b;
        #pragma unroll
        for (int o = 1; o < 32; o <<= 1) { u32 t = __shfl_up_sync(FULLM, bi, o); if (lane >= o) bi += t; }
        if (lane == 31) scrI[warp] = (int)(tA + bi);   // warp's 64-digit total
        __syncthreads();
        int cross = 0;
        #pragma unroll
        for (int j = 0; j < 8; ++j) { int v = scrI[j]; if (j < warp) cross += v; }
        dbase[d0] = cross + (int)(ai - a);
        dbase[d1] = cross + (int)tA + (int)(bi - b);
    }
    __syncthreads();

    // scatter: pos = digit base + warp-exclusive base + within-warp rank
    #pragma unroll
    for (int e = 0; e < EPN; ++e) {
        u32 k = items[e];
        int d  = MASK ? ((int)(k >> SHIFT) & 511) : (int)(k >> SHIFT);
        int rk = (int)((e < 4 ? (lr0 >> (e * 8)) : (lr1 >> ((e - 4) * 8))) & 255u);
        int pos = dbase[d] + (int)wrow[d] + rk;
        if (LAST) {
            int idx = (int)(k & 0x7FFu);
            s_arr[pos] = theta[idx];      // exact sorted theta value
            perm[pos]  = (u16)idx;
        } else if (SWZ) {
            int sp = (pos & ~255) | ((pos & 31) << 3) | ((pos >> 5) & 7);
            keyA[sp] = k;
        } else {
            keyA[pos] = k;
        }
    }
    __syncthreads();
}

__global__ void __launch_bounds__(THREADS, 5)
soft_spearman_kernel(const float* __restrict__ x1,
                     const float* __restrict__ x2,
                     float* __restrict__ out)
{
    // Static smem 36KB + small statics (5 blocks/SM):
    //  [0    , 8192 ) keyA u32[2048] -> s_arr (sorted theta, desc)
    //  [8192 ,16384) theta (orig order) -> ststart u16[2048] (PAV)
    //  [16384,24576) whist u16[8][512] (sort) -> stack_cv f32[2048] (PAV)
    //  [24576,28672) perm u16[2048] (low 11 bits idx, bit15 boundary)
    //  [28672,36864) rank1 f32[2048] (live across r)
    __shared__ __align__(16) unsigned char sraw[36864];
    __shared__ int   dbase[512];
    __shared__ int   scrI[8];
    __shared__ float scrA[8];
    __shared__ float scrB[8];
    __shared__ float scrC[8];

    u32*   keyA     = (u32*)sraw;
    float* s_arr    = (float*)sraw;
    float* theta    = (float*)(sraw + 8192);
    u16*   ststart  = (u16*)(sraw + 8192);
    u16*   whist    = (u16*)(sraw + 16384);
    float* stack_cv = (float*)(sraw + 16384);
    u16*   perm     = (u16*)(sraw + 24576);
    float* rank1    = (float*)(sraw + 28672);

    const int row  = blockIdx.x;
    const int tid  = threadIdx.x;
    const int warp = tid >> 5;
    const int lane = tid & 31;
    const u32 lt   = (1u << lane) - 1u;

    const float M1 = 1024.5f;   // exact mean of ranks: (N+1)/2

    float asq0 = 0.0f, asq1 = 0.0f, adot = 0.0f;   // deferred moments

    for (int r = 0; r < 2; ++r) {
        const float* x = (r == 0 ? x1 : x2) + (size_t)row * N;

        // ---- build keys + theta table (vectorized) ----
        u32 items[EPN];
        const float4* xv = (const float4*)x;
        #pragma unroll
        for (int q = 0; q < 2; ++q) {
            float4 f4 = xv[tid * 2 + q];
            float4 tf;
            tf.x = f4.x * 10.0f; tf.y = f4.y * 10.0f;
            tf.z = f4.z * 10.0f; tf.w = f4.w * 10.0f;
            ((float4*)theta)[tid * 2 + q] = tf;
            float fs[4] = {tf.x, tf.y, tf.z, tf.w};
            #pragma unroll
            for (int c2 = 0; c2 < 4; ++c2) {
                int i = tid * 8 + q * 4 + c2;
                u32 u = __float_as_uint(fs[c2]);
                u = (u & 0x80000000u) ? ~u : (u | 0x80000000u);   // order-preserving
                u32 t = (~u) >> 14;                                // 18-bit ascending key
                items[q * 4 + c2] = (t << 11) | (u32)i;            // [key:18][idx:11]
            }
        }

        // ---- 2 stable passes x 9 bits over key bits [11,29) ----
        radix_pass9<false, true , 11, true >(items, whist, dbase, scrI, keyA, s_arr, perm, theta, tid, warp, lane, lt);
        {
            const uint4* kv = (const uint4*)keyA;
            int b4 = warp * 64 + lane * 2;
            uint4 g0 = kv[b4];
            uint4 g1 = kv[b4 + 1];
            items[0] = g0.x; items[1] = g0.y; items[2] = g0.z; items[3] = g0.w;
            items[4] = g1.x; items[5] = g1.y; items[6] = g1.z; items[7] = g1.w;
        }
        radix_pass9<true , false, 20, false>(items, whist, dbase, scrI, keyA, s_arr, perm, theta, tid, warp, lane, lt);
        // s_arr / perm complete (pass ends with syncthreads)

        // ---- boundary flags via prefix-min / suffix-max shuffle scans on v0 ----
        {
            int base = tid * EPN;
            float c[8];
            float4 q0 = *(float4*)(s_arr + base);
            float4 q1 = *(float4*)(s_arr + base + 4);
            c[0]=q0.x; c[1]=q0.y; c[2]=q0.z; c[3]=q0.w;
            c[4]=q1.x; c[5]=q1.y; c[6]=q1.z; c[7]=q1.w;
            #pragma unroll
            for (int e = 0; e < 8; ++e)
                c[e] -= __logf((float)(N - base - e));   // v0 = s - log(N-i)
            float cmin = c[0], cmax = c[0];
            #pragma unroll
            for (int e = 1; e < 8; ++e) { cmin = fminf(cmin, c[e]); cmax = fmaxf(cmax, c[e]); }

            float pm = cmin;
            #pragma unroll
            for (int o = 1; o < 32; o <<= 1) {
                float t = __shfl_up_sync(FULLM, pm, o);
                if (lane >= o) pm = fminf(pm, t);
            }
            float sm = cmax;
            #pragma unroll
            for (int o = 1; o < 32; o <<= 1) {
                float t = __shfl_down_sync(FULLM, sm, o);
                if (lane < 32 - o) sm = fmaxf(sm, t);
            }
            if (lane == 31) scrA[warp] = pm;
            if (lane == 0)  scrB[warp] = sm;
            __syncthreads();
            float preW = 3.0e38f, sufW = -3.0e38f;
            #pragma unroll
            for (int j = 0; j < 8; ++j) {
                float wm = scrA[j], wx = scrB[j];
                if (j < warp) preW = fminf(preW, wm);
                if (j > warp) sufW = fmaxf(sufW, wx);
            }
            float pmPrev = __shfl_up_sync(FULLM, pm, 1);
            float pexcl  = (lane == 0)  ? preW : fminf(preW, pmPrev);
            float smNext = __shfl_down_sync(FULLM, sm, 1);
            float sexcl  = (lane == 31) ? sufW : fmaxf(sufW, smNext);

            float suf[8];
            float t = sexcl;
            #pragma unroll
            for (int e = 7; e >= 0; --e) { suf[e] = fmaxf(c[e], t); t = suf[e]; }
            float run = pexcl;
            #pragma unroll
            for (int e = 0; e < 8; ++e) {
                run = fminf(run, c[e]);
                float nxt = (e < 7) ? suf[e + 1] : sexcl;
                if (run > nxt) perm[base + e] |= 0x8000;   // guaranteed boundary
            }
            __syncthreads();
        }

        // ---- segmented PAV + fused emit, with MLP-batched preloads ----
        // sum of ranks == N(N+1)/2 exactly; only sum(rk^2) and centered dot kept.
        float asq = 0.0f;

        // branch-free preload: all flags/indices for this thread's 8 strided
        // slots issue back-to-back (MLP=16), instead of a serial LDS chain.
        u32 pm0[EPN], pmprev[EPN];
        #pragma unroll
        for (int k = 0; k < EPN; ++k) {
            int i0 = tid + k * THREADS;
            pm0[k]    = perm[i0];
            pmprev[k] = (i0 == 0) ? 0x8000u : (u32)perm[i0 - 1];
        }
        float r1v[EPN];
        if (r == 1) {
            #pragma unroll
            for (int k = 0; k < EPN; ++k)          // speculative gather, MLP=8
                r1v[k] = rank1[pm0[k] & 0x7FFu];
        }

        #pragma unroll 1
        for (int k = 0; k < EPN; ++k) {
            if (!(pmprev[k] & 0x8000u)) continue;   // not a segment start
            int i0 = tid + k * THREADS;

            // singleton fast path: entirely register-resident
            if ((pm0[k] & 0x8000u) || i0 == N - 1) {
                float rk = (float)(N - i0);
                int   p  = (int)(pm0[k] & 0x7FFu);
                if (r == 0) { rank1[p] = rk; asq += rk * rk; }
                else        { asq += rk * rk; adot += rk * (r1v[k] - M1); }
                continue;
            }

            float cly    = s_arr[i0];                       // lse_y of current block
            int   W      = N - i0;                          // exact weight sum
            float cv     = cly - __logf((float)W);
            int   cstart = i0;
            int   top    = -1;
            int   i      = i0;

            while (i + 1 < N && !(perm[i] & 0x8000)) {
                ++i;
                float si  = s_arr[i];
                float lwi = __logf((float)(N - i));
                float vi  = si - lwi;
                if (cv > vi) {
                    ++top;
                    stack_cv[i0 + top] = cv;
                    ststart [i0 + top] = (u16)cstart;
                    cly = si; W = N - i; cv = vi; cstart = i;
                } else {
                    cly = logaddexpf_(cly, si);
                    W  += (N - i);
                    cv  = cly - __logf((float)W);
                    while (top >= 0) {
                        float pcv = stack_cv[i0 + top];
                        if (pcv > cv) break;
                        int pstart = ststart[i0 + top];
                        int Wp = ((2 * N - pstart - cstart + 1) * (cstart - pstart)) >> 1;
                        float ply = pcv + __logf((float)Wp);
                        cly = logaddexpf_(ply, cly);
                        W  += Wp;
                        cv  = cly - __logf((float)W);
                        cstart = pstart;
                        --top;
                    }
                }
            }

            // emit blocks back-to-front
            int eend = i;
            for (;;) {
                for (int j = cstart; j <= eend; ++j) {
                    float rk = __expf(s_arr[j] - cv);
                    int   p  = perm[j] & 0x7FF;
                    if (r == 0) { rank1[p] = rk; asq += rk * rk; }
                    else        { asq += rk * rk; adot += rk * (rank1[p] - M1); }
                }
                if (top < 0) break;
                eend   = cstart - 1;
                cv     = stack_cv[i0 + top];
                cstart = ststart[i0 + top];
                --top;
            }
        }
        if (r == 0) asq0 = asq; else asq1 = asq;
        __syncthreads();   // rank1/stack_cv/s_arr quiesce before next phase
    }

    // ---- single block reduction of the three deferred moments ----
    #pragma unroll
    for (int o = 16; o > 0; o >>= 1) {
        asq0 += __shfl_down_sync(FULLM, asq0, o);
        asq1 += __shfl_down_sync(FULLM, asq1, o);
        adot += __shfl_down_sync(FULLM, adot, o);
    }
    if (lane == 0) { scrA[warp] = asq0; scrB[warp] = asq1; scrC[warp] = adot; }
    __syncthreads();
    if (tid == 0) {
        float Q1 = 0.0f, Q2 = 0.0f, D = 0.0f;
        #pragma unroll
        for (int w2 = 0; w2 < 8; ++w2) { Q1 += scrA[w2]; Q2 += scrB[w2]; D += scrC[w2]; }
        const float SSN = 2149581312.0f;   // (N(N+1)/2)^2 / N = 512 * 2049^2, exact
        float v1 = Q1 - SSN;
        float v2 = Q2 - SSN;
        out[row] = 1.0f - D / (sqrtf(v1) * sqrtf(v2));
    }
}

extern "C" void kernel_launch(void* const* d_in, const int* in_sizes, int n_in,
                              void* d_out, int out_size)
{
    const float* x1 = (const float*)d_in[0];
    const float* x2 = (const float*)d_in[1];
    float* out = (float*)d_out;
    int rows = in_sizes[0] / N;   // 4096
    soft_spearman_kernel<<<rows, THREADS>>>(x1, x2, out);
}

// round 16
// speedup vs baseline: 1.1008x; 1.1008x over previous
#include <cuda_runtime.h>
#include <math.h>

#define N        2048
#define THREADS  256
#define EPN      8
#define FULLM    0xFFFFFFFFu

typedef unsigned int   u32;
typedef unsigned short u16;

__device__ __forceinline__ float logaddexpf_(float a, float b) {
    float mx = fmaxf(a, b);
    float mn = fminf(a, b);
    return mx + __logf(1.0f + __expf(mn - mx));
}

// One stable 9-bit radix pass on u32 keys, in-place.
// Item order contract: items[e] is sorted-position warp*256 + e*32 + lane.
// If SWZ: scatter writes key for position p at swizzled address
//   sigma(p) = (p&~255)|((p&31)<<3)|((p>>5)&7), so next gather is 2x LDS.128.
// If LAST: scatter emits s/perm at TRUE positions via theta[idx].
template <bool LAST, bool SWZ, int SHIFT, bool MASK>
__device__ __forceinline__ void radix_pass9(
    const u32 items[EPN],
    u16* __restrict__ whist, int* __restrict__ dbase, int* __restrict__ scrI,
    u32* __restrict__ keyA, float* __restrict__ s_arr, u16* __restrict__ perm,
    const float* __restrict__ theta,
    int tid, int warp, int lane, u32 lt)
{
    // zero OWN warp's histogram row (1024B = 64 uint4); __syncwarp suffices.
    {
        uint4 z = make_uint4(0, 0, 0, 0);
        uint4* wz = (uint4*)(whist + (warp << 9));
        wz[lane]      = z;
        wz[lane + 32] = z;
        __syncwarp();
    }

    // ranking: per-warp running counts; processing order == position order
    u16* wrow = whist + warp * 512;
    u32 lr0 = 0, lr1 = 0;
    #pragma unroll
    for (int e = 0; e < EPN; ++e) {
        int d = MASK ? ((int)(items[e] >> SHIFT) & 511) : (int)(items[e] >> SHIFT);
        u32 m = __match_any_sync(FULLM, d);
        int lr = __popc(m & lt);
        u32 prior = wrow[d];
        u32 rk = prior + (u32)lr;           // within-warp stable rank for digit d
        if (e < 4) lr0 |= rk << (e * 8);
        else       lr1 |= rk << ((e - 4) * 8);
        if ((m & lt) == 0)                  // leader bumps running count
            wrow[d] = (u16)(prior + __popc(m));
        if (e < EPN - 1) __syncwarp();      // last iter ordered by the barrier below
    }
    __syncthreads();   // all gathers complete too (in-place safety)

    // distributed scan: warp w owns digits [64w, 64w+64), 2 per lane.
    {
        int d0 = (warp << 6) + lane;
        int d1 = d0 + 32;
        u32 run0 = 0, run1 = 0;
        #pragma unroll
        for (int w8 = 0; w8 < 8; ++w8) {
            u16* rowp = whist + (w8 << 9);
            u32 v0 = rowp[d0]; rowp[d0] = (u16)run0; run0 += v0;
            u32 v1 = rowp[d1]; rowp[d1] = (u16)run1; run1 += v1;
        }
        u32 a = run0, ai = a;
        #pragma unroll
        for (int o = 1; o < 32; o <<= 1) { u32 t = __shfl_up_sync(FULLM, ai, o); if (lane >= o) ai += t; }
        u32 tA = __shfl_sync(FULLM, ai, 31);
        u32 b = run1, bi = b;
        #pragma unroll
        for (int o = 1; o < 32; o <<= 1) { u32 t = __shfl_up_sync(FULLM, bi, o); if (lane >= o) bi += t; }
        if (lane == 31) scrI[warp] = (int)(tA + bi);   // warp's 64-digit total
        __syncthreads();
        int cross = 0;
        #pragma unroll
        for (int j = 0; j < 8; ++j) { int v = scrI[j]; if (j < warp) cross += v; }
        dbase[d0] = cross + (int)(ai - a);
        dbase[d1] = cross + (int)tA + (int)(bi - b);
    }
    __syncthreads();

    // scatter: pos = digit base + warp-exclusive base + within-warp rank
    #pragma unroll
    for (int e = 0; e < EPN; ++e) {
        u32 k = items[e];
        int d  = MASK ? ((int)(k >> SHIFT) & 511) : (int)(k >> SHIFT);
        int rk = (int)((e < 4 ? (lr0 >> (e * 8)) : (lr1 >> ((e - 4) * 8))) & 255u);
        int pos = dbase[d] + (int)wrow[d] + rk;
        if (LAST) {
            int idx = (int)(k & 0x7FFu);
            s_arr[pos] = theta[idx];      // exact sorted theta value
            perm[pos]  = (u16)idx;
        } else if (SWZ) {
            int sp = (pos & ~255) | ((pos & 31) << 3) | ((pos >> 5) & 7);
            keyA[sp] = k;
        } else {
            keyA[pos] = k;
        }
    }
    __syncthreads();
}

__global__ void __launch_bounds__(THREADS, 5)
soft_spearman_kernel(const float* __restrict__ x1,
                     const float* __restrict__ x2,
                     float* __restrict__ out)
{
    // Static smem 36KB + small statics (5 blocks/SM):
    //  [0    , 8192 ) keyA u32[2048] -> s_arr (sorted theta, desc)
    //  [8192 ,16384) theta (orig order) -> ststart u16[2048] (PAV)
    //  [16384,24576) whist u16[8][512] (sort) -> stack_cv f32[2048] (PAV)
    //  [24576,28672) perm u16[2048] (low 11 bits idx, bit15 boundary)
    //  [28672,36864) rank1 f32[2048] (live across r)
    __shared__ __align__(16) unsigned char sraw[36864];
    __shared__ int   dbase[512];
    __shared__ int   scrI[8];
    __shared__ float scrA[8];
    __shared__ float scrB[8];
    __shared__ float scrC[8];

    u32*   keyA     = (u32*)sraw;
    float* s_arr    = (float*)sraw;
    float* theta    = (float*)(sraw + 8192);
    u16*   ststart  = (u16*)(sraw + 8192);
    u16*   whist    = (u16*)(sraw + 16384);
    float* stack_cv = (float*)(sraw + 16384);
    u16*   perm     = (u16*)(sraw + 24576);
    float* rank1    = (float*)(sraw + 28672);

    const int row  = blockIdx.x;
    const int tid  = threadIdx.x;
    const int warp = tid >> 5;
    const int lane = tid & 31;
    const u32 lt   = (1u << lane) - 1u;

    const float M1 = 1024.5f;   // exact mean of ranks: (N+1)/2

    float asq0 = 0.0f, asq1 = 0.0f, adot = 0.0f;   // deferred moments

    for (int r = 0; r < 2; ++r) {
        const float* x = (r == 0 ? x1 : x2) + (size_t)row * N;

        // ---- build keys + theta table (vectorized) ----
        u32 items[EPN];
        const float4* xv = (const float4*)x;
        #pragma unroll
        for (int q = 0; q < 2; ++q) {
            float4 f4 = xv[tid * 2 + q];
            float4 tf;
            tf.x = f4.x * 10.0f; tf.y = f4.y * 10.0f;
            tf.z = f4.z * 10.0f; tf.w = f4.w * 10.0f;
            ((float4*)theta)[tid * 2 + q] = tf;
            float fs[4] = {tf.x, tf.y, tf.z, tf.w};
            #pragma unroll
            for (int c2 = 0; c2 < 4; ++c2) {
                int i = tid * 8 + q * 4 + c2;
                u32 u = __float_as_uint(fs[c2]);
                u = (u & 0x80000000u) ? ~u : (u | 0x80000000u);   // order-preserving
                u32 t = (~u) >> 14;                                // 18-bit ascending key
                items[q * 4 + c2] = (t << 11) | (u32)i;            // [key:18][idx:11]
            }
        }

        // ---- 2 stable passes x 9 bits over key bits [11,29) ----
        radix_pass9<false, true , 11, true >(items, whist, dbase, scrI, keyA, s_arr, perm, theta, tid, warp, lane, lt);
        {
            const uint4* kv = (const uint4*)keyA;
            int b4 = warp * 64 + lane * 2;
            uint4 g0 = kv[b4];
            uint4 g1 = kv[b4 + 1];
            items[0] = g0.x; items[1] = g0.y; items[2] = g0.z; items[3] = g0.w;
            items[4] = g1.x; items[5] = g1.y; items[6] = g1.z; items[7] = g1.w;
        }
        radix_pass9<true , false, 20, false>(items, whist, dbase, scrI, keyA, s_arr, perm, theta, tid, warp, lane, lt);
        // s_arr / perm complete (pass ends with syncthreads)

        // ---- boundary flags via prefix-min / suffix-max shuffle scans on v0 ----
        {
            int base = tid * EPN;
            float c[8];
            float4 q0 = *(float4*)(s_arr + base);
            float4 q1 = *(float4*)(s_arr + base + 4);
            c[0]=q0.x; c[1]=q0.y; c[2]=q0.z; c[3]=q0.w;
            c[4]=q1.x; c[5]=q1.y; c[6]=q1.z; c[7]=q1.w;
            #pragma unroll
            for (int e = 0; e < 8; ++e)
                c[e] -= __logf((float)(N - base - e));   // v0 = s - log(N-i)
            float cmin = c[0], cmax = c[0];
            #pragma unroll
            for (int e = 1; e < 8; ++e) { cmin = fminf(cmin, c[e]); cmax = fmaxf(cmax, c[e]); }

            float pm = cmin;
            #pragma unroll
            for (int o = 1; o < 32; o <<= 1) {
                float t = __shfl_up_sync(FULLM, pm, o);
                if (lane >= o) pm = fminf(pm, t);
            }
            float sm = cmax;
            #pragma unroll
            for (int o = 1; o < 32; o <<= 1) {
                float t = __shfl_down_sync(FULLM, sm, o);
                if (lane < 32 - o) sm = fmaxf(sm, t);
            }
            if (lane == 31) scrA[warp] = pm;
            if (lane == 0)  scrB[warp] = sm;
            __syncthreads();
            float preW = 3.0e38f, sufW = -3.0e38f;
            #pragma unroll
            for (int j = 0; j < 8; ++j) {
                float wm = scrA[j], wx = scrB[j];
                if (j < warp) preW = fminf(preW, wm);
                if (j > warp) sufW = fmaxf(sufW, wx);
            }
            float pmPrev = __shfl_up_sync(FULLM, pm, 1);
            float pexcl  = (lane == 0)  ? preW : fminf(preW, pmPrev);
            float smNext = __shfl_down_sync(FULLM, sm, 1);
            float sexcl  = (lane == 31) ? sufW : fmaxf(sufW, smNext);

            float suf[8];
            float t = sexcl;
            #pragma unroll
            for (int e = 7; e >= 0; --e) { suf[e] = fmaxf(c[e], t); t = suf[e]; }
            float run = pexcl;
            #pragma unroll
            for (int e = 0; e < 8; ++e) {
                run = fminf(run, c[e]);
                float nxt = (e < 7) ? suf[e + 1] : sexcl;
                if (run > nxt) perm[base + e] |= 0x8000;   // guaranteed boundary
            }
            __syncthreads();
        }

        // ---- segmented PAV (closed-form weights, cv-only stack) + fused emit ----
        // sum of ranks == N(N+1)/2 exactly, so only sum(rk^2) and the centered
        // dot are accumulated (reduced once, after both rows).
        float asq = 0.0f;

        for (int i0 = tid; i0 < N; i0 += THREADS) {
            bool isStart = (i0 == 0) || (perm[i0 - 1] & 0x8000);
            if (!isStart) continue;

            // singleton fast path
            if ((perm[i0] & 0x8000) || i0 == N - 1) {
                float rk = (float)(N - i0);
                int   p  = perm[i0] & 0x7FF;
                if (r == 0) { rank1[p] = rk; asq += rk * rk; }
                else        { asq += rk * rk; adot += rk * (rank1[p] - M1); }
                continue;
            }

            float cly    = s_arr[i0];                       // lse_y of current block
            int   W      = N - i0;                          // exact weight sum
            float cv     = cly - __logf((float)W);
            int   cstart = i0;
            int   top    = -1;
            int   i      = i0;

            while (i + 1 < N && !(perm[i] & 0x8000)) {
                ++i;
                float si  = s_arr[i];
                float lwi = __logf((float)(N - i));
                float vi  = si - lwi;
                if (cv > vi) {
                    ++top;
                    stack_cv[i0 + top] = cv;
                    ststart [i0 + top] = (u16)cstart;
                    cly = si; W = N - i; cv = vi; cstart = i;
                } else {
                    cly = logaddexpf_(cly, si);
                    W  += (N - i);
                    cv  = cly - __logf((float)W);
                    while (top >= 0) {
                        float pcv = stack_cv[i0 + top];
                        if (pcv > cv) break;
                        int pstart = ststart[i0 + top];
                        int Wp = ((2 * N - pstart - cstart + 1) * (cstart - pstart)) >> 1;
                        float ply = pcv + __logf((float)Wp);
                        cly = logaddexpf_(ply, cly);
                        W  += Wp;
                        cv  = cly - __logf((float)W);
                        cstart = pstart;
                        --top;
                    }
                }
            }

            // emit blocks back-to-front
            int eend = i;
            for (;;) {
                for (int j = cstart; j <= eend; ++j) {
                    float rk = __expf(s_arr[j] - cv);
                    int   p  = perm[j] & 0x7FF;
                    if (r == 0) { rank1[p] = rk; asq += rk * rk; }
                    else        { asq += rk * rk; adot += rk * (rank1[p] - M1); }
                }
                if (top < 0) break;
                eend   = cstart - 1;
                cv     = stack_cv[i0 + top];
                cstart = ststart[i0 + top];
                --top;
            }
        }
        if (r == 0) asq0 = asq; else asq1 = asq;
        __syncthreads();   // rank1/stack_cv/s_arr quiesce before next phase
    }

    // ---- single block reduction of the three deferred moments ----
    #pragma unroll
    for (int o = 16; o > 0; o >>= 1) {
        asq0 += __shfl_down_sync(FULLM, asq0, o);
        asq1 += __shfl_down_sync(FULLM, asq1, o);
        adot += __shfl_down_sync(FULLM, adot, o);
    }
    if (lane == 0) { scrA[warp] = asq0; scrB[warp] = asq1; scrC[warp] = adot; }
    __syncthreads();
    if (tid == 0) {
        float Q1 = 0.0f, Q2 = 0.0f, D = 0.0f;
        #pragma unroll
        for (int w2 = 0; w2 < 8; ++w2) { Q1 += scrA[w2]; Q2 += scrB[w2]; D += scrC[w2]; }
        const float SSN = 2149581312.0f;   // (N(N+1)/2)^2 / N = 512 * 2049^2, exact
        float v1 = Q1 - SSN;
        float v2 = Q2 - SSN;
        out[row] = 1.0f - D / (sqrtf(v1) * sqrtf(v2));
    }
}

extern "C" void kernel_launch(void* const* d_in, const int* in_sizes, int n_in,
                              void* d_out, int out_size)
{
    const float* x1 = (const float*)d_in[0];
    const float* x2 = (const float*)d_in[1];
    float* out = (float*)d_out;
    int rows = in_sizes[0] / N;   // 4096
    soft_spearman_kernel<<<rows, THREADS>>>(x1, x2, out);
}